// round 14
// baseline (speedup 1.0000x reference)
#include <cuda_runtime.h>
#include <cstdint>

#define AREAS   10
#define NPA     192
#define CDIM    128
#define NDIM    1920
#define MROWS   32768
#define OUTC    1280
#define CHUNK_M 4096
#define NCHUNK  (MROWS / CHUNK_M)     // 8
#define KT      12
#define PR      8
#define MB_N    (CHUNK_M / 128)       // 32
#define NBUF    3

#define SROW_P  1924

#define XG_BUF_F ((size_t)MB_N * AREAS * KT * 2048)
__device__ float g_xg[NBUF * XG_BUF_F];
__device__ float g_Wt[AREAS * KT * 128 * 16];   // [a][kt][n][kr][i]
__device__ int   g_src[NDIM];
__device__ int   g_gperm[NDIM];

__device__ __forceinline__ float cvt_tf32(float v) {
    uint32_t u;
    asm("cvt.rna.tf32.f32 %0, %1;" : "=r"(u) : "f"(v));
    return __uint_as_float(u);
}

#define CP_ASYNC16(dst, src) \
    asm volatile("cp.async.cg.shared.global [%0], [%1], 16;" :: "r"(dst), "l"(src))
#define CP_COMMIT() asm volatile("cp.async.commit_group;" ::: "memory")
#define CP_WAIT0()  asm volatile("cp.async.wait_group 0;" ::: "memory")

// ---------------------------------------------------------------------------
// Merged setup: warps 0-9 build src, then all 512 threads build gperm.
// ---------------------------------------------------------------------------
__global__ void srcgperm_kernel(const int* __restrict__ nr) {
    const int tid = threadIdx.x;
    const int warp = tid >> 5, lane = tid & 31;
    if (warp < AREAS) {
        int cnt = 0;
        for (int base = 0; base < NDIM; base += 32) {
            const int n = base + lane;
            const bool m = (nr[n] == warp);
            const unsigned bal = __ballot_sync(0xffffffffu, m);
            if (m) g_src[warp * NPA + cnt + __popc(bal & ((1u << lane) - 1u))] = n;
            cnt += __popc(bal);
        }
    }
    __syncthreads();
    for (int q = tid; q < NDIM; q += 512) {
        int i   = q & 3;
        int kr  = (q >> 2) & 3;
        int akt = q >> 4;
        int a = akt / KT, kt = akt % KT;
        g_gperm[q] = g_src[a * NPA + kt * 16 + kr + 4 * i];
    }
}

__global__ void wcvt_kernel(const float* __restrict__ W) {
    int o = blockIdx.x * 256 + threadIdx.x;
    if (o < AREAS * KT * 128 * 16) {
        int i  = o & 3;
        int kr = (o >> 2) & 3;
        int n  = (o >> 4) & 127;
        int kt = (o >> 11) % KT;
        int a  = o / (KT * 128 * 16);
        int k  = kt * 16 + kr + 4 * i;
        g_Wt[o] = cvt_tf32(W[(a * NPA + k) * CDIM + n]);
    }
}

// ---------------------------------------------------------------------------
// Permute (exact R8 version): 8 rows/block, per-warp coalesced slab stores.
// ---------------------------------------------------------------------------
__global__ __launch_bounds__(256, 3)
void permute_kernel(const float* __restrict__ x, int chunk_row0, int buf) {
    __shared__ float srow[PR * SROW_P];
    const int tid  = threadIdx.x;
    const int warp = tid >> 5, lane = tid & 31;
    const int r0   = blockIdx.x * PR;
    const int mb   = r0 >> 7;
    const int rloc = r0 & 127;

    const float4* x4 = (const float4*)(x + ((size_t)chunk_row0 + r0) * NDIM);
    #pragma unroll
    for (int s = 0; s < (PR * NDIM / 4) / 256; s++) {
        int i = tid + s * 256;
        int row = i / 480, c4 = i % 480;
        *(float4*)(srow + row * SROW_P + c4 * 4) = x4[i];
    }
    __syncthreads();

    const int row = lane >> 2;
    const int kr  = lane & 3;
    const float* sr = srow + row * SROW_P;
    float* xgb = g_xg + (size_t)buf * XG_BUF_F;
    const size_t slab0 = (size_t)mb * (AREAS * KT);
    const int dst_off = (rloc + row) * 16 + kr * 4;

    #pragma unroll
    for (int it = 0; it < (AREAS * KT) / 8; it++) {      // 15 iters
        const int akt = warp * 15 + it;
        const int4 g = *(const int4*)(g_gperm + (akt * 4 + kr) * 4);
        float4 v;
        v.x = cvt_tf32(sr[g.x]);
        v.y = cvt_tf32(sr[g.y]);
        v.z = cvt_tf32(sr[g.z]);
        v.w = cvt_tf32(sr[g.w]);
        *(float4*)(xgb + (slab0 + akt) * 2048 + dst_off) = v;
    }
}

// ---------------------------------------------------------------------------
// GEMM (exact R8 version): block=(mb, a) 128x128, 96KB B slab, 2 CTAs/SM.
// ---------------------------------------------------------------------------
#define B_SLAB_F (KT * 128 * 16)
#define SMEM_BYTES (B_SLAB_F * 4)     // 98304

__global__ __launch_bounds__(256, 2)
void gemm_kernel(const float* __restrict__ bias, float* __restrict__ out,
                 int chunk_row0, int buf) {
    extern __shared__ float Bs[];
    const int a    = blockIdx.y;
    const int mb   = blockIdx.x;
    const int tid  = threadIdx.x;
    const int warp = tid >> 5, lane = tid & 31;
    const int wm = warp >> 1;
    const int wn = warp & 1;
    const int qr = lane >> 2;
    const int kr = lane & 3;

    const float* Wsl = g_Wt + (size_t)a * B_SLAB_F;
    #pragma unroll
    for (int s = 0; s < (B_SLAB_F / 4) / 256; s++) {
        int i = tid + s * 256;
        uint32_t dst = (uint32_t)__cvta_generic_to_shared(Bs + i * 4);
        CP_ASYNC16(dst, Wsl + (size_t)i * 4);
    }
    CP_COMMIT();

    float2 bv[8];
    #pragma unroll
    for (int nt = 0; nt < 8; nt++)
        bv[nt] = *(const float2*)(bias + a * CDIM + wn * 64 + nt * 8 + kr * 2);

    const int roff[2] = { wm * 32 + qr, wm * 32 + 8 + qr };

    const float* Ag = g_xg + (size_t)buf * XG_BUF_F
                    + ((size_t)mb * AREAS + a) * KT * 2048;
    float4 areg[2][2];
    #pragma unroll
    for (int mt = 0; mt < 2; mt++)
        #pragma unroll
        for (int h = 0; h < 2; h++)
            areg[mt][h] = *(const float4*)(Ag + (roff[h] + mt * 16) * 16 + kr * 4);

    float acc[2][8][4];
    #pragma unroll
    for (int i = 0; i < 2; i++)
        #pragma unroll
        for (int j = 0; j < 8; j++)
            #pragma unroll
            for (int k = 0; k < 4; k++) acc[i][j][k] = 0.f;

    CP_WAIT0();
    __syncthreads();

    #pragma unroll
    for (int kt = 0; kt < KT; kt++) {
        float4 curA[2][2];
        #pragma unroll
        for (int mt = 0; mt < 2; mt++)
            #pragma unroll
            for (int h = 0; h < 2; h++) curA[mt][h] = areg[mt][h];

        if (kt + 1 < KT) {
            const float* An = Ag + (kt + 1) * 2048;
            #pragma unroll
            for (int mt = 0; mt < 2; mt++)
                #pragma unroll
                for (int h = 0; h < 2; h++)
                    areg[mt][h] = *(const float4*)(An + (roff[h] + mt * 16) * 16 + kr * 4);
        }

        float4 bfr[8];
        #pragma unroll
        for (int nt = 0; nt < 8; nt++) {
            int n = wn * 64 + nt * 8 + qr;
            bfr[nt] = *(const float4*)(Bs + (kt * 128 + n) * 16 + kr * 4);
        }

        #pragma unroll
        for (int k8 = 0; k8 < 2; k8++) {
            #pragma unroll
            for (int mt = 0; mt < 2; mt++) {
                uint32_t a0, a1, a2, a3;
                if (k8 == 0) {
                    a0 = __float_as_uint(curA[mt][0].x);
                    a1 = __float_as_uint(curA[mt][1].x);
                    a2 = __float_as_uint(curA[mt][0].y);
                    a3 = __float_as_uint(curA[mt][1].y);
                } else {
                    a0 = __float_as_uint(curA[mt][0].z);
                    a1 = __float_as_uint(curA[mt][1].z);
                    a2 = __float_as_uint(curA[mt][0].w);
                    a3 = __float_as_uint(curA[mt][1].w);
                }
                #pragma unroll
                for (int nt = 0; nt < 8; nt++) {
                    uint32_t b0 = __float_as_uint(k8 == 0 ? bfr[nt].x : bfr[nt].z);
                    uint32_t b1 = __float_as_uint(k8 == 0 ? bfr[nt].y : bfr[nt].w);
                    asm volatile(
                        "mma.sync.aligned.m16n8k8.row.col.f32.tf32.tf32.f32 "
                        "{%0,%1,%2,%3},{%4,%5,%6,%7},{%8,%9},{%0,%1,%2,%3};"
                        : "+f"(acc[mt][nt][0]), "+f"(acc[mt][nt][1]),
                          "+f"(acc[mt][nt][2]), "+f"(acc[mt][nt][3])
                        : "r"(a0), "r"(a1), "r"(a2), "r"(a3), "r"(b0), "r"(b1));
                }
            }
        }
    }

    #pragma unroll
    for (int mt = 0; mt < 2; mt++) {
        const int r0g = chunk_row0 + mb * 128 + wm * 32 + mt * 16 + qr;
        #pragma unroll
        for (int nt = 0; nt < 8; nt++) {
            const int c = wn * 64 + nt * 8 + kr * 2;
            float2 v0 = make_float2(acc[mt][nt][0] + bv[nt].x, acc[mt][nt][1] + bv[nt].y);
            float2 v1 = make_float2(acc[mt][nt][2] + bv[nt].x, acc[mt][nt][3] + bv[nt].y);
            *(float2*)(out + (size_t)r0g * OUTC + a * CDIM + c) = v0;
            *(float2*)(out + (size_t)(r0g + 8) * OUTC + a * CDIM + c) = v1;
        }
    }
}

// ---------------------------------------------------------------------------
extern "C" void kernel_launch(void* const* d_in, const int* in_sizes, int n_in,
                              void* d_out, int out_size) {
    const float* x    = (const float*)d_in[0];
    const float* W    = (const float*)d_in[1];
    const float* bias = (const float*)d_in[2];
    const int*   nr   = (const int*)  d_in[3];
    float* out = (float*)d_out;

    static bool inited = false;
    static cudaStream_t sP;
    static cudaEvent_t evFork, evP[NCHUNK], evG[NCHUNK];
    if (!inited) {
        cudaFuncSetAttribute(gemm_kernel,
                             cudaFuncAttributeMaxDynamicSharedMemorySize, SMEM_BYTES);
        cudaStreamCreateWithFlags(&sP, cudaStreamNonBlocking);
        cudaEventCreateWithFlags(&evFork, cudaEventDisableTiming);
        for (int i = 0; i < NCHUNK; i++) {
            cudaEventCreateWithFlags(&evP[i], cudaEventDisableTiming);
            cudaEventCreateWithFlags(&evG[i], cudaEventDisableTiming);
        }
        inited = true;
    }

    // fork: permute-side setup runs on sP concurrently with wcvt on stream 0
    cudaEventRecord(evFork, 0);
    cudaStreamWaitEvent(sP, evFork, 0);

    srcgperm_kernel<<<1, 512, 0, sP>>>(nr);
    wcvt_kernel<<<(AREAS * KT * 128 * 16 + 255) / 256, 256>>>(W);

    for (int ch = 0; ch < NCHUNK; ch++) {
        const int row0 = ch * CHUNK_M;
        const int buf  = ch % NBUF;

        if (ch >= NBUF) cudaStreamWaitEvent(sP, evG[ch - NBUF], 0);
        permute_kernel<<<CHUNK_M / PR, 256, 0, sP>>>(x, row0, buf);
        cudaEventRecord(evP[ch], sP);

        cudaStreamWaitEvent(0, evP[ch], 0);
        gemm_kernel<<<dim3(MB_N, AREAS), 256, SMEM_BYTES>>>(bias, out, row0, buf);
        cudaEventRecord(evG[ch], 0);
    }
}

// round 15
// speedup vs baseline: 1.3358x; 1.3358x over previous
#include <cuda_runtime.h>
#include <cstdint>

#define AREAS   10
#define NPA     192
#define CDIM    128
#define NDIM    1920
#define MROWS   32768
#define OUTC    1280
#define CHUNK_M 4096
#define NCHUNK  (MROWS / CHUNK_M)     // 8
#define KT      12
#define PR      8
#define MB_N    (CHUNK_M / 128)       // 32
#define NBUF    2

#define SROW_P  1924

#define XG_BUF_F ((size_t)MB_N * AREAS * KT * 2048)
__device__ float g_xg[NBUF * XG_BUF_F];
__device__ float g_Wt[AREAS * KT * 128 * 16];   // [a][kt][n][kr][i]
__device__ int   g_src[NDIM];
__device__ int   g_gperm[NDIM];

__device__ __forceinline__ float cvt_tf32(float v) {
    uint32_t u;
    asm("cvt.rna.tf32.f32 %0, %1;" : "=r"(u) : "f"(v));
    return __uint_as_float(u);
}

#define CP_ASYNC16(dst, src) \
    asm volatile("cp.async.cg.shared.global [%0], [%1], 16;" :: "r"(dst), "l"(src))
#define CP_COMMIT() asm volatile("cp.async.commit_group;" ::: "memory")
#define CP_WAIT0()  asm volatile("cp.async.wait_group 0;" ::: "memory")

// ---------------------------------------------------------------------------
// Merged setup: warps 0-9 build src, then all 512 threads build gperm.
// ---------------------------------------------------------------------------
__global__ void srcgperm_kernel(const int* __restrict__ nr) {
    const int tid = threadIdx.x;
    const int warp = tid >> 5, lane = tid & 31;
    if (warp < AREAS) {
        int cnt = 0;
        for (int base = 0; base < NDIM; base += 32) {
            const int n = base + lane;
            const bool m = (nr[n] == warp);
            const unsigned bal = __ballot_sync(0xffffffffu, m);
            if (m) g_src[warp * NPA + cnt + __popc(bal & ((1u << lane) - 1u))] = n;
            cnt += __popc(bal);
        }
    }
    __syncthreads();
    for (int q = tid; q < NDIM; q += 512) {
        int i   = q & 3;
        int kr  = (q >> 2) & 3;
        int akt = q >> 4;
        int a = akt / KT, kt = akt % KT;
        g_gperm[q] = g_src[a * NPA + kt * 16 + kr + 4 * i];
    }
}

__global__ void wcvt_kernel(const float* __restrict__ W) {
    int o = blockIdx.x * 256 + threadIdx.x;
    if (o < AREAS * KT * 128 * 16) {
        int i  = o & 3;
        int kr = (o >> 2) & 3;
        int n  = (o >> 4) & 127;
        int kt = (o >> 11) % KT;
        int a  = o / (KT * 128 * 16);
        int k  = kt * 16 + kr + 4 * i;
        g_Wt[o] = cvt_tf32(W[(a * NPA + k) * CDIM + n]);
    }
}

// ---------------------------------------------------------------------------
// Permute (exact R8): 8 rows/block, per-warp coalesced slab stores.
// ---------------------------------------------------------------------------
__global__ __launch_bounds__(256, 3)
void permute_kernel(const float* __restrict__ x, int chunk_row0, int buf) {
    __shared__ float srow[PR * SROW_P];
    const int tid  = threadIdx.x;
    const int warp = tid >> 5, lane = tid & 31;
    const int r0   = blockIdx.x * PR;
    const int mb   = r0 >> 7;
    const int rloc = r0 & 127;

    const float4* x4 = (const float4*)(x + ((size_t)chunk_row0 + r0) * NDIM);
    #pragma unroll
    for (int s = 0; s < (PR * NDIM / 4) / 256; s++) {
        int i = tid + s * 256;
        int row = i / 480, c4 = i % 480;
        *(float4*)(srow + row * SROW_P + c4 * 4) = x4[i];
    }
    __syncthreads();

    const int row = lane >> 2;
    const int kr  = lane & 3;
    const float* sr = srow + row * SROW_P;
    float* xgb = g_xg + (size_t)buf * XG_BUF_F;
    const size_t slab0 = (size_t)mb * (AREAS * KT);
    const int dst_off = (rloc + row) * 16 + kr * 4;

    #pragma unroll
    for (int it = 0; it < (AREAS * KT) / 8; it++) {      // 15 iters
        const int akt = warp * 15 + it;
        const int4 g = *(const int4*)(g_gperm + (akt * 4 + kr) * 4);
        float4 v;
        v.x = cvt_tf32(sr[g.x]);
        v.y = cvt_tf32(sr[g.y]);
        v.z = cvt_tf32(sr[g.z]);
        v.w = cvt_tf32(sr[g.w]);
        *(float4*)(xgb + (slab0 + akt) * 2048 + dst_off) = v;
    }
}

// ---------------------------------------------------------------------------
// GEMM (exact R8): block=(mb, a) 128x128, 96KB B slab, 2 CTAs/SM.
// ---------------------------------------------------------------------------
#define B_SLAB_F (KT * 128 * 16)
#define SMEM_BYTES (B_SLAB_F * 4)     // 98304

__global__ __launch_bounds__(256, 2)
void gemm_kernel(const float* __restrict__ bias, float* __restrict__ out,
                 int chunk_row0, int buf) {
    extern __shared__ float Bs[];
    const int a    = blockIdx.y;
    const int mb   = blockIdx.x;
    const int tid  = threadIdx.x;
    const int warp = tid >> 5, lane = tid & 31;
    const int wm = warp >> 1;
    const int wn = warp & 1;
    const int qr = lane >> 2;
    const int kr = lane & 3;

    const float* Wsl = g_Wt + (size_t)a * B_SLAB_F;
    #pragma unroll
    for (int s = 0; s < (B_SLAB_F / 4) / 256; s++) {
        int i = tid + s * 256;
        uint32_t dst = (uint32_t)__cvta_generic_to_shared(Bs + i * 4);
        CP_ASYNC16(dst, Wsl + (size_t)i * 4);
    }
    CP_COMMIT();

    float2 bv[8];
    #pragma unroll
    for (int nt = 0; nt < 8; nt++)
        bv[nt] = *(const float2*)(bias + a * CDIM + wn * 64 + nt * 8 + kr * 2);

    const int roff[2] = { wm * 32 + qr, wm * 32 + 8 + qr };

    const float* Ag = g_xg + (size_t)buf * XG_BUF_F
                    + ((size_t)mb * AREAS + a) * KT * 2048;
    float4 areg[2][2];
    #pragma unroll
    for (int mt = 0; mt < 2; mt++)
        #pragma unroll
        for (int h = 0; h < 2; h++)
            areg[mt][h] = *(const float4*)(Ag + (roff[h] + mt * 16) * 16 + kr * 4);

    float acc[2][8][4];
    #pragma unroll
    for (int i = 0; i < 2; i++)
        #pragma unroll
        for (int j = 0; j < 8; j++)
            #pragma unroll
            for (int k = 0; k < 4; k++) acc[i][j][k] = 0.f;

    CP_WAIT0();
    __syncthreads();

    #pragma unroll
    for (int kt = 0; kt < KT; kt++) {
        float4 curA[2][2];
        #pragma unroll
        for (int mt = 0; mt < 2; mt++)
            #pragma unroll
            for (int h = 0; h < 2; h++) curA[mt][h] = areg[mt][h];

        if (kt + 1 < KT) {
            const float* An = Ag + (kt + 1) * 2048;
            #pragma unroll
            for (int mt = 0; mt < 2; mt++)
                #pragma unroll
                for (int h = 0; h < 2; h++)
                    areg[mt][h] = *(const float4*)(An + (roff[h] + mt * 16) * 16 + kr * 4);
        }

        float4 bfr[8];
        #pragma unroll
        for (int nt = 0; nt < 8; nt++) {
            int n = wn * 64 + nt * 8 + qr;
            bfr[nt] = *(const float4*)(Bs + (kt * 128 + n) * 16 + kr * 4);
        }

        #pragma unroll
        for (int k8 = 0; k8 < 2; k8++) {
            #pragma unroll
            for (int mt = 0; mt < 2; mt++) {
                uint32_t a0, a1, a2, a3;
                if (k8 == 0) {
                    a0 = __float_as_uint(curA[mt][0].x);
                    a1 = __float_as_uint(curA[mt][1].x);
                    a2 = __float_as_uint(curA[mt][0].y);
                    a3 = __float_as_uint(curA[mt][1].y);
                } else {
                    a0 = __float_as_uint(curA[mt][0].z);
                    a1 = __float_as_uint(curA[mt][1].z);
                    a2 = __float_as_uint(curA[mt][0].w);
                    a3 = __float_as_uint(curA[mt][1].w);
                }
                #pragma unroll
                for (int nt = 0; nt < 8; nt++) {
                    uint32_t b0 = __float_as_uint(k8 == 0 ? bfr[nt].x : bfr[nt].z);
                    uint32_t b1 = __float_as_uint(k8 == 0 ? bfr[nt].y : bfr[nt].w);
                    asm volatile(
                        "mma.sync.aligned.m16n8k8.row.col.f32.tf32.tf32.f32 "
                        "{%0,%1,%2,%3},{%4,%5,%6,%7},{%8,%9},{%0,%1,%2,%3};"
                        : "+f"(acc[mt][nt][0]), "+f"(acc[mt][nt][1]),
                          "+f"(acc[mt][nt][2]), "+f"(acc[mt][nt][3])
                        : "r"(a0), "r"(a1), "r"(a2), "r"(a3), "r"(b0), "r"(b1));
                }
            }
        }
    }

    #pragma unroll
    for (int mt = 0; mt < 2; mt++) {
        const int r0g = chunk_row0 + mb * 128 + wm * 32 + mt * 16 + qr;
        #pragma unroll
        for (int nt = 0; nt < 8; nt++) {
            const int c = wn * 64 + nt * 8 + kr * 2;
            float2 v0 = make_float2(acc[mt][nt][0] + bv[nt].x, acc[mt][nt][1] + bv[nt].y);
            float2 v1 = make_float2(acc[mt][nt][2] + bv[nt].x, acc[mt][nt][3] + bv[nt].y);
            *(float2*)(out + (size_t)r0g * OUTC + a * CDIM + c) = v0;
            *(float2*)(out + (size_t)(r0g + 8) * OUTC + a * CDIM + c) = v1;
        }
    }
}

// ---------------------------------------------------------------------------
extern "C" void kernel_launch(void* const* d_in, const int* in_sizes, int n_in,
                              void* d_out, int out_size) {
    const float* x    = (const float*)d_in[0];
    const float* W    = (const float*)d_in[1];
    const float* bias = (const float*)d_in[2];
    const int*   nr   = (const int*)  d_in[3];
    float* out = (float*)d_out;

    static bool inited = false;
    static cudaStream_t sP;
    static cudaEvent_t evFork, evP[NCHUNK], evG[NCHUNK];
    if (!inited) {
        cudaFuncSetAttribute(gemm_kernel,
                             cudaFuncAttributeMaxDynamicSharedMemorySize, SMEM_BYTES);
        cudaStreamCreateWithFlags(&sP, cudaStreamNonBlocking);
        cudaEventCreateWithFlags(&evFork, cudaEventDisableTiming);
        for (int i = 0; i < NCHUNK; i++) {
            cudaEventCreateWithFlags(&evP[i], cudaEventDisableTiming);
            cudaEventCreateWithFlags(&evG[i], cudaEventDisableTiming);
        }
        inited = true;
    }

    // fork: permute-side setup on sP concurrent with wcvt on stream 0
    cudaEventRecord(evFork, 0);
    cudaStreamWaitEvent(sP, evFork, 0);

    srcgperm_kernel<<<1, 512, 0, sP>>>(nr);
    wcvt_kernel<<<(AREAS * KT * 128 * 16 + 255) / 256, 256>>>(W);

    for (int ch = 0; ch < NCHUNK; ch++) {
        const int row0 = ch * CHUNK_M;
        const int buf  = ch & 1;

        if (ch >= 2) cudaStreamWaitEvent(sP, evG[ch - 2], 0);
        permute_kernel<<<CHUNK_M / PR, 256, 0, sP>>>(x, row0, buf);
        cudaEventRecord(evP[ch], sP);

        cudaStreamWaitEvent(0, evP[ch], 0);
        gemm_kernel<<<dim3(MB_N, AREAS), 256, SMEM_BYTES>>>(bias, out, row0, buf);
        cudaEventRecord(evG[ch], 0);
    }
}

// round 16
// speedup vs baseline: 1.7761x; 1.3296x over previous
#include <cuda_runtime.h>
#include <cuda_fp16.h>
#include <cstdint>

#define AREAS   10
#define NPA     192
#define CDIM    128
#define NDIM    1920
#define MROWS   32768
#define OUTC    1280
#define CHUNK_M 4096
#define NCHUNK  (MROWS / CHUNK_M)     // 8
#define KTP     6                     // 6 kt-pairs (K=32 each; 2 MMA-K16 steps)
#define PR      8
#define MB_N    (CHUNK_M / 128)       // 32
#define NBUF    2

#define SROW_P  1924

// xg: [buf][(mb*AREAS+a)*KTP + ktp][r 128][kr 4][kp 2][4 halfs]  (fp16)
#define SLAB_H  4096                  // 128 * 32 halfs per (mb,a,ktp)
#define XG_BUF_H ((size_t)MB_N * AREAS * KTP * SLAB_H)
__device__ __align__(16) __half g_xg[NBUF * XG_BUF_H];
// Wt: [a][ktp][n 128][kr 4][kp 2][4 halfs]
__device__ __align__(16) __half g_Wt[AREAS * KTP * SLAB_H];
__device__ int   g_src[NDIM];
__device__ int   g_gperm[NDIM];       // [(a*12+kt)*4+kr] int4: cols for k=2kr,2kr+1,2kr+8,2kr+9

#define CP_ASYNC16(dst, src) \
    asm volatile("cp.async.cg.shared.global [%0], [%1], 16;" :: "r"(dst), "l"(src))
#define CP_COMMIT() asm volatile("cp.async.commit_group;" ::: "memory")
#define CP_WAIT0()  asm volatile("cp.async.wait_group 0;" ::: "memory")

__device__ __forceinline__ uint32_t pack_h2(float a, float b) {
    __half2 h = __halves2half2(__float2half_rn(a), __float2half_rn(b));
    return *(uint32_t*)&h;
}

// ---------------------------------------------------------------------------
// Setup: warps 0-9 build src; then gperm with fp16 fragment k-offsets.
// ---------------------------------------------------------------------------
__global__ void srcgperm_kernel(const int* __restrict__ nr) {
    const int tid = threadIdx.x;
    const int warp = tid >> 5, lane = tid & 31;
    if (warp < AREAS) {
        int cnt = 0;
        for (int base = 0; base < NDIM; base += 32) {
            const int n = base + lane;
            const bool m = (nr[n] == warp);
            const unsigned bal = __ballot_sync(0xffffffffu, m);
            if (m) g_src[warp * NPA + cnt + __popc(bal & ((1u << lane) - 1u))] = n;
            cnt += __popc(bal);
        }
    }
    __syncthreads();
    for (int q = tid; q < NDIM; q += 512) {
        int i   = q & 3;
        int kr  = (q >> 2) & 3;
        int akt = q >> 4;
        int a = akt / 12, kt = akt % 12;
        int koff = 2 * kr + (i & 1) + 8 * (i >> 1);
        g_gperm[q] = g_src[a * NPA + kt * 16 + koff];
    }
}

// Wt[a][ktp][n][kr][kp][i] = half(W[a][(ktp*2+kp)*16 + 2kr+(i&1)+8*(i>>1)][n])
__global__ void wcvt_kernel(const float* __restrict__ W) {
    int o = blockIdx.x * 256 + threadIdx.x;
    if (o < AREAS * KTP * SLAB_H) {
        int i   = o & 3;
        int kp  = (o >> 2) & 1;
        int kr  = (o >> 3) & 3;
        int n   = (o >> 5) & 127;
        int ktp = (o >> 12) % KTP;
        int a   = o / (KTP * SLAB_H);
        int k   = (ktp * 2 + kp) * 16 + 2 * kr + (i & 1) + 8 * (i >> 1);
        g_Wt[o] = __float2half_rn(W[(a * NPA + k) * CDIM + n]);
    }
}

// ---------------------------------------------------------------------------
// Permute: 8 rows/block. lane=(row,kr); per (a,ktp): gather 8 x-vals,
// pack to 8 halfs, one 16B store -> warp covers contiguous 512B.
// ---------------------------------------------------------------------------
__global__ __launch_bounds__(256, 3)
void permute_kernel(const float* __restrict__ x, int chunk_row0, int buf) {
    __shared__ float srow[PR * SROW_P];
    const int tid  = threadIdx.x;
    const int warp = tid >> 5, lane = tid & 31;
    const int r0   = blockIdx.x * PR;
    const int mb   = r0 >> 7;
    const int rloc = r0 & 127;

    const float4* x4 = (const float4*)(x + ((size_t)chunk_row0 + r0) * NDIM);
    #pragma unroll
    for (int s = 0; s < (PR * NDIM / 4) / 256; s++) {
        int i = tid + s * 256;
        int row = i / 480, c4 = i % 480;
        *(float4*)(srow + row * SROW_P + c4 * 4) = x4[i];
    }
    __syncthreads();

    const int row = lane >> 2;
    const int kr  = lane & 3;
    const float* sr = srow + row * SROW_P;
    __half* xgb = g_xg + (size_t)buf * XG_BUF_H;
    const int dst_off = (rloc + row) * 32 + kr * 8;      // halfs

    #pragma unroll
    for (int it = 0; it < 8; it++) {
        const int aktp = warp + it * 8;                  // 0..59
        if (aktp < AREAS * KTP) {
            const int a   = aktp / KTP;
            const int ktl = aktp - a * KTP;
            const int akt0 = a * 12 + ktl * 2;
            const int4 g0 = *(const int4*)(g_gperm + (akt0 * 4 + kr) * 4);
            const int4 g1 = *(const int4*)(g_gperm + ((akt0 + 1) * 4 + kr) * 4);
            uint4 v;
            v.x = pack_h2(sr[g0.x], sr[g0.y]);
            v.y = pack_h2(sr[g0.z], sr[g0.w]);
            v.z = pack_h2(sr[g1.x], sr[g1.y]);
            v.w = pack_h2(sr[g1.z], sr[g1.w]);
            __half* slab = xgb + ((size_t)(mb * AREAS + a) * KTP + ktl) * SLAB_H;
            *(uint4*)(slab + dst_off) = v;
        }
    }
}

// ---------------------------------------------------------------------------
// GEMM fp16: block=(mb,a) 128x128, 8 warps 4Mx2N (warp 32x64).
// B slab 48KB in SMEM, 2 CTAs/SM. Per ktp (K=32): 4 A LDG.128, 8 B LDS.128,
// 32 m16n8k16 MMAs. A double-buffered by compile-time parity.
// ---------------------------------------------------------------------------
#define B_SLAB_H (KTP * SLAB_H)       // 24576 halfs = 48KB
#define SMEM_BYTES (B_SLAB_H * 2)

__global__ __launch_bounds__(256, 2)
void gemm_kernel(const float* __restrict__ bias, float* __restrict__ out,
                 int chunk_row0, int buf) {
    extern __shared__ __half Bs[];
    const int a    = blockIdx.y;
    const int mb   = blockIdx.x;
    const int tid  = threadIdx.x;
    const int warp = tid >> 5, lane = tid & 31;
    const int wm = warp >> 1;
    const int wn = warp & 1;
    const int qr = lane >> 2;
    const int kr = lane & 3;

    const __half* Wsl = g_Wt + (size_t)a * B_SLAB_H;
    #pragma unroll
    for (int s = 0; s < 12; s++) {                       // 3072 x 16B
        int i = tid + s * 256;
        uint32_t dst = (uint32_t)__cvta_generic_to_shared(Bs + i * 8);
        CP_ASYNC16(dst, Wsl + (size_t)i * 8);
    }
    CP_COMMIT();

    float2 bv[8];
    #pragma unroll
    for (int nt = 0; nt < 8; nt++)
        bv[nt] = *(const float2*)(bias + a * CDIM + wn * 64 + nt * 8 + kr * 2);

    const int roff[2] = { wm * 32 + qr, wm * 32 + 8 + qr };

    const __half* Ag = g_xg + (size_t)buf * XG_BUF_H
                     + ((size_t)(mb * AREAS + a)) * (KTP * SLAB_H);

    // abuf[parity][mt][h]: 16B = both kp fragments for one row
    uint4 abuf[2][2][2];
    #pragma unroll
    for (int mt = 0; mt < 2; mt++)
        #pragma unroll
        for (int h = 0; h < 2; h++)
            abuf[0][mt][h] = *(const uint4*)(Ag + (roff[h] + mt * 16) * 32 + kr * 8);

    float acc[2][8][4];
    #pragma unroll
    for (int i = 0; i < 2; i++)
        #pragma unroll
        for (int j = 0; j < 8; j++)
            #pragma unroll
            for (int k = 0; k < 4; k++) acc[i][j][k] = 0.f;

    CP_WAIT0();
    __syncthreads();

    #pragma unroll
    for (int ktp = 0; ktp < KTP; ktp++) {
        const int cur = ktp & 1;
        if (ktp + 1 < KTP) {
            const __half* An = Ag + (ktp + 1) * SLAB_H;
            #pragma unroll
            for (int mt = 0; mt < 2; mt++)
                #pragma unroll
                for (int h = 0; h < 2; h++)
                    abuf[cur ^ 1][mt][h] =
                        *(const uint4*)(An + (roff[h] + mt * 16) * 32 + kr * 8);
        }

        // nt in halves of 4 to bound register pressure
        #pragma unroll
        for (int nth = 0; nth < 2; nth++) {
            uint4 bf[4];
            #pragma unroll
            for (int nt4 = 0; nt4 < 4; nt4++) {
                int n = wn * 64 + (nth * 4 + nt4) * 8 + qr;
                bf[nt4] = *(const uint4*)(Bs + (ktp * 128 + n) * 32 + kr * 8);
            }
            #pragma unroll
            for (int kp = 0; kp < 2; kp++) {
                #pragma unroll
                for (int mt = 0; mt < 2; mt++) {
                    const uint32_t a0 = kp ? abuf[cur][mt][0].z : abuf[cur][mt][0].x;
                    const uint32_t a1 = kp ? abuf[cur][mt][1].z : abuf[cur][mt][1].x;
                    const uint32_t a2 = kp ? abuf[cur][mt][0].w : abuf[cur][mt][0].y;
                    const uint32_t a3 = kp ? abuf[cur][mt][1].w : abuf[cur][mt][1].y;
                    #pragma unroll
                    for (int nt4 = 0; nt4 < 4; nt4++) {
                        const int nt = nth * 4 + nt4;
                        const uint32_t b0 = kp ? bf[nt4].z : bf[nt4].x;
                        const uint32_t b1 = kp ? bf[nt4].w : bf[nt4].y;
                        asm volatile(
                            "mma.sync.aligned.m16n8k16.row.col.f32.f16.f16.f32 "
                            "{%0,%1,%2,%3},{%4,%5,%6,%7},{%8,%9},{%0,%1,%2,%3};"
                            : "+f"(acc[mt][nt][0]), "+f"(acc[mt][nt][1]),
                              "+f"(acc[mt][nt][2]), "+f"(acc[mt][nt][3])
                            : "r"(a0), "r"(a1), "r"(a2), "r"(a3), "r"(b0), "r"(b1));
                    }
                }
            }
        }
    }

    #pragma unroll
    for (int mt = 0; mt < 2; mt++) {
        const int r0g = chunk_row0 + mb * 128 + wm * 32 + mt * 16 + qr;
        #pragma unroll
        for (int nt = 0; nt < 8; nt++) {
            const int c = wn * 64 + nt * 8 + kr * 2;
            float2 v0 = make_float2(acc[mt][nt][0] + bv[nt].x, acc[mt][nt][1] + bv[nt].y);
            float2 v1 = make_float2(acc[mt][nt][2] + bv[nt].x, acc[mt][nt][3] + bv[nt].y);
            *(float2*)(out + (size_t)r0g * OUTC + a * CDIM + c) = v0;
            *(float2*)(out + (size_t)(r0g + 8) * OUTC + a * CDIM + c) = v1;
        }
    }
}

// ---------------------------------------------------------------------------
extern "C" void kernel_launch(void* const* d_in, const int* in_sizes, int n_in,
                              void* d_out, int out_size) {
    const float* x    = (const float*)d_in[0];
    const float* W    = (const float*)d_in[1];
    const float* bias = (const float*)d_in[2];
    const int*   nr   = (const int*)  d_in[3];
    float* out = (float*)d_out;

    static bool inited = false;
    static cudaStream_t sP;
    static cudaEvent_t evFork, evP[NCHUNK], evG[NCHUNK];
    if (!inited) {
        cudaFuncSetAttribute(gemm_kernel,
                             cudaFuncAttributeMaxDynamicSharedMemorySize, SMEM_BYTES);
        cudaStreamCreateWithFlags(&sP, cudaStreamNonBlocking);
        cudaEventCreateWithFlags(&evFork, cudaEventDisableTiming);
        for (int i = 0; i < NCHUNK; i++) {
            cudaEventCreateWithFlags(&evP[i], cudaEventDisableTiming);
            cudaEventCreateWithFlags(&evG[i], cudaEventDisableTiming);
        }
        inited = true;
    }

    cudaEventRecord(evFork, 0);
    cudaStreamWaitEvent(sP, evFork, 0);

    srcgperm_kernel<<<1, 512, 0, sP>>>(nr);
    wcvt_kernel<<<(AREAS * KTP * SLAB_H + 255) / 256, 256>>>(W);

    for (int ch = 0; ch < NCHUNK; ch++) {
        const int row0 = ch * CHUNK_M;
        const int buf  = ch & 1;

        if (ch >= 2) cudaStreamWaitEvent(sP, evG[ch - 2], 0);
        permute_kernel<<<CHUNK_M / PR, 256, 0, sP>>>(x, row0, buf);
        cudaEventRecord(evP[ch], sP);

        cudaStreamWaitEvent(0, evP[ch], 0);
        gemm_kernel<<<dim3(MB_N, AREAS), 256, SMEM_BYTES>>>(bias, out, row0, buf);
        cudaEventRecord(evG[ch], 0);
    }
}

// round 17
// speedup vs baseline: 1.7767x; 1.0003x over previous
#include <cuda_runtime.h>
#include <cuda_fp16.h>
#include <cstdint>

#define AREAS   10
#define NPA     192
#define CDIM    128
#define NDIM    1920
#define MROWS   32768
#define OUTC    1280
#define CHUNK_M 4096
#define NCHUNK  (MROWS / CHUNK_M)     // 8
#define KTP     6                     // 6 kt-pairs (K=32 each; 2 MMA-K16 steps)
#define PR      8
#define MB_N    (CHUNK_M / 128)       // 32
#define NBUF    2

#define SROW_P  1924

// xg: [buf][(mb*AREAS+a)*KTP + ktp][r 128][kr 4][kp 2][4 halfs]  (fp16)
#define SLAB_H  4096                  // 128 * 32 halfs per (mb,a,ktp)
#define XG_BUF_H ((size_t)MB_N * AREAS * KTP * SLAB_H)
__device__ __align__(16) __half g_xg[NBUF * XG_BUF_H];
// Wt: [a][ktp][n 128][kr 4][kp 2][4 halfs]
__device__ __align__(16) __half g_Wt[AREAS * KTP * SLAB_H];
__device__ int   g_src[NDIM];
__device__ int   g_gperm[NDIM];       // [(a*12+kt)*4+kr] int4: cols for k=2kr,2kr+1,2kr+8,2kr+9

#define CP_ASYNC16(dst, src) \
    asm volatile("cp.async.cg.shared.global [%0], [%1], 16;" :: "r"(dst), "l"(src))
#define CP_COMMIT() asm volatile("cp.async.commit_group;" ::: "memory")
#define CP_WAIT0()  asm volatile("cp.async.wait_group 0;" ::: "memory")

__device__ __forceinline__ uint32_t pack_h2(float a, float b) {
    __half2 h = __halves2half2(__float2half_rn(a), __float2half_rn(b));
    return *(uint32_t*)&h;
}

// ---------------------------------------------------------------------------
// Setup: warps 0-9 build src; then gperm with fp16 fragment k-offsets.
// ---------------------------------------------------------------------------
__global__ void srcgperm_kernel(const int* __restrict__ nr) {
    const int tid = threadIdx.x;
    const int warp = tid >> 5, lane = tid & 31;
    if (warp < AREAS) {
        int cnt = 0;
        for (int base = 0; base < NDIM; base += 32) {
            const int n = base + lane;
            const bool m = (nr[n] == warp);
            const unsigned bal = __ballot_sync(0xffffffffu, m);
            if (m) g_src[warp * NPA + cnt + __popc(bal & ((1u << lane) - 1u))] = n;
            cnt += __popc(bal);
        }
    }
    __syncthreads();
    for (int q = tid; q < NDIM; q += 512) {
        int i   = q & 3;
        int kr  = (q >> 2) & 3;
        int akt = q >> 4;
        int a = akt / 12, kt = akt % 12;
        int koff = 2 * kr + (i & 1) + 8 * (i >> 1);
        g_gperm[q] = g_src[a * NPA + kt * 16 + koff];
    }
}

// Wt[a][ktp][n][kr][kp][i] = half(W[a][(ktp*2+kp)*16 + 2kr+(i&1)+8*(i>>1)][n])
__global__ void wcvt_kernel(const float* __restrict__ W) {
    int o = blockIdx.x * 256 + threadIdx.x;
    if (o < AREAS * KTP * SLAB_H) {
        int i   = o & 3;
        int kp  = (o >> 2) & 1;
        int kr  = (o >> 3) & 3;
        int n   = (o >> 5) & 127;
        int ktp = (o >> 12) % KTP;
        int a   = o / (KTP * SLAB_H);
        int k   = (ktp * 2 + kp) * 16 + 2 * kr + (i & 1) + 8 * (i >> 1);
        g_Wt[o] = __float2half_rn(W[(a * NPA + k) * CDIM + n]);
    }
}

// ---------------------------------------------------------------------------
// Permute: 8 rows/block (unchanged from R16).
// ---------------------------------------------------------------------------
__global__ __launch_bounds__(256, 3)
void permute_kernel(const float* __restrict__ x, int chunk_row0, int buf) {
    __shared__ float srow[PR * SROW_P];
    const int tid  = threadIdx.x;
    const int warp = tid >> 5, lane = tid & 31;
    const int r0   = blockIdx.x * PR;
    const int mb   = r0 >> 7;
    const int rloc = r0 & 127;

    const float4* x4 = (const float4*)(x + ((size_t)chunk_row0 + r0) * NDIM);
    #pragma unroll
    for (int s = 0; s < (PR * NDIM / 4) / 256; s++) {
        int i = tid + s * 256;
        int row = i / 480, c4 = i % 480;
        *(float4*)(srow + row * SROW_P + c4 * 4) = x4[i];
    }
    __syncthreads();

    const int row = lane >> 2;
    const int kr  = lane & 3;
    const float* sr = srow + row * SROW_P;
    __half* xgb = g_xg + (size_t)buf * XG_BUF_H;
    const int dst_off = (rloc + row) * 32 + kr * 8;      // halfs

    #pragma unroll
    for (int it = 0; it < 8; it++) {
        const int aktp = warp + it * 8;                  // 0..59
        if (aktp < AREAS * KTP) {
            const int a   = aktp / KTP;
            const int ktl = aktp - a * KTP;
            const int akt0 = a * 12 + ktl * 2;
            const int4 g0 = *(const int4*)(g_gperm + (akt0 * 4 + kr) * 4);
            const int4 g1 = *(const int4*)(g_gperm + ((akt0 + 1) * 4 + kr) * 4);
            uint4 v;
            v.x = pack_h2(sr[g0.x], sr[g0.y]);
            v.y = pack_h2(sr[g0.z], sr[g0.w]);
            v.z = pack_h2(sr[g1.x], sr[g1.y]);
            v.w = pack_h2(sr[g1.z], sr[g1.w]);
            __half* slab = xgb + ((size_t)(mb * AREAS + a) * KTP + ktl) * SLAB_H;
            *(uint4*)(slab + dst_off) = v;
        }
    }
}

// ---------------------------------------------------------------------------
// GEMM fp16: block=(mb,a) 128x128. BOTH A (48KB) and B (48KB) staged to
// SMEM via one cp.async burst; mainloop entirely LDS-fed (29-cyc latency,
// hidden) instead of L2 LDG (~260 cyc, previously exposed). 2 CTAs/SM.
// ---------------------------------------------------------------------------
#define SLAB_TOTAL_H (KTP * SLAB_H)   // 24576 halfs = 48KB each
#define SMEM_BYTES (2 * SLAB_TOTAL_H * 2)   // 96KB

__global__ __launch_bounds__(256, 2)
void gemm_kernel(const float* __restrict__ bias, float* __restrict__ out,
                 int chunk_row0, int buf) {
    extern __shared__ __half Sm[];
    __half* As = Sm;                         // 24576 halfs
    __half* Bs = Sm + SLAB_TOTAL_H;          // 24576 halfs
    const int a    = blockIdx.y;
    const int mb   = blockIdx.x;
    const int tid  = threadIdx.x;
    const int warp = tid >> 5, lane = tid & 31;
    const int wm = warp >> 1;
    const int wn = warp & 1;
    const int qr = lane >> 2;
    const int kr = lane & 3;

    const __half* Asrc = g_xg + (size_t)buf * XG_BUF_H
                       + ((size_t)(mb * AREAS + a)) * SLAB_TOTAL_H;
    const __half* Wsl  = g_Wt + (size_t)a * SLAB_TOTAL_H;
    #pragma unroll
    for (int s = 0; s < 12; s++) {           // 3072 x 16B each matrix
        int i = tid + s * 256;
        CP_ASYNC16((uint32_t)__cvta_generic_to_shared(As + (size_t)i * 8),
                   Asrc + (size_t)i * 8);
        CP_ASYNC16((uint32_t)__cvta_generic_to_shared(Bs + (size_t)i * 8),
                   Wsl + (size_t)i * 8);
    }
    CP_COMMIT();

    float2 bv[8];
    #pragma unroll
    for (int nt = 0; nt < 8; nt++)
        bv[nt] = *(const float2*)(bias + a * CDIM + wn * 64 + nt * 8 + kr * 2);

    const int roff[2] = { wm * 32 + qr, wm * 32 + 8 + qr };

    float acc[2][8][4];
    #pragma unroll
    for (int i = 0; i < 2; i++)
        #pragma unroll
        for (int j = 0; j < 8; j++)
            #pragma unroll
            for (int k = 0; k < 4; k++) acc[i][j][k] = 0.f;

    CP_WAIT0();
    __syncthreads();

    #pragma unroll
    for (int ktp = 0; ktp < KTP; ktp++) {
        // A fragments for this ktp: 4 conflict-free LDS.128
        uint4 af[2][2];
        #pragma unroll
        for (int mt = 0; mt < 2; mt++)
            #pragma unroll
            for (int h = 0; h < 2; h++)
                af[mt][h] = *(const uint4*)(As + ktp * SLAB_H
                                            + (roff[h] + mt * 16) * 32 + kr * 8);

        #pragma unroll
        for (int nth = 0; nth < 2; nth++) {
            uint4 bf[4];
            #pragma unroll
            for (int nt4 = 0; nt4 < 4; nt4++) {
                int n = wn * 64 + (nth * 4 + nt4) * 8 + qr;
                bf[nt4] = *(const uint4*)(Bs + (ktp * 128 + n) * 32 + kr * 8);
            }
            #pragma unroll
            for (int kp = 0; kp < 2; kp++) {
                #pragma unroll
                for (int mt = 0; mt < 2; mt++) {
                    const uint32_t a0 = kp ? af[mt][0].z : af[mt][0].x;
                    const uint32_t a1 = kp ? af[mt][1].z : af[mt][1].x;
                    const uint32_t a2 = kp ? af[mt][0].w : af[mt][0].y;
                    const uint32_t a3 = kp ? af[mt][1].w : af[mt][1].y;
                    #pragma unroll
                    for (int nt4 = 0; nt4 < 4; nt4++) {
                        const int nt = nth * 4 + nt4;
                        const uint32_t b0 = kp ? bf[nt4].z : bf[nt4].x;
                        const uint32_t b1 = kp ? bf[nt4].w : bf[nt4].y;
                        asm volatile(
                            "mma.sync.aligned.m16n8k16.row.col.f32.f16.f16.f32 "
                            "{%0,%1,%2,%3},{%4,%5,%6,%7},{%8,%9},{%0,%1,%2,%3};"
                            : "+f"(acc[mt][nt][0]), "+f"(acc[mt][nt][1]),
                              "+f"(acc[mt][nt][2]), "+f"(acc[mt][nt][3])
                            : "r"(a0), "r"(a1), "r"(a2), "r"(a3), "r"(b0), "r"(b1));
                    }
                }
            }
        }
    }

    #pragma unroll
    for (int mt = 0; mt < 2; mt++) {
        const int r0g = chunk_row0 + mb * 128 + wm * 32 + mt * 16 + qr;
        #pragma unroll
        for (int nt = 0; nt < 8; nt++) {
            const int c = wn * 64 + nt * 8 + kr * 2;
            float2 v0 = make_float2(acc[mt][nt][0] + bv[nt].x, acc[mt][nt][1] + bv[nt].y);
            float2 v1 = make_float2(acc[mt][nt][2] + bv[nt].x, acc[mt][nt][3] + bv[nt].y);
            *(float2*)(out + (size_t)r0g * OUTC + a * CDIM + c) = v0;
            *(float2*)(out + (size_t)(r0g + 8) * OUTC + a * CDIM + c) = v1;
        }
    }
}

// ---------------------------------------------------------------------------
extern "C" void kernel_launch(void* const* d_in, const int* in_sizes, int n_in,
                              void* d_out, int out_size) {
    const float* x    = (const float*)d_in[0];
    const float* W    = (const float*)d_in[1];
    const float* bias = (const float*)d_in[2];
    const int*   nr   = (const int*)  d_in[3];
    float* out = (float*)d_out;

    static bool inited = false;
    static cudaStream_t sP;
    static cudaEvent_t evFork, evP[NCHUNK], evG[NCHUNK];
    if (!inited) {
        cudaFuncSetAttribute(gemm_kernel,
                             cudaFuncAttributeMaxDynamicSharedMemorySize, SMEM_BYTES);
        cudaStreamCreateWithFlags(&sP, cudaStreamNonBlocking);
        cudaEventCreateWithFlags(&evFork, cudaEventDisableTiming);
        for (int i = 0; i < NCHUNK; i++) {
            cudaEventCreateWithFlags(&evP[i], cudaEventDisableTiming);
            cudaEventCreateWithFlags(&evG[i], cudaEventDisableTiming);
        }
        inited = true;
    }

    cudaEventRecord(evFork, 0);
    cudaStreamWaitEvent(sP, evFork, 0);

    srcgperm_kernel<<<1, 512, 0, sP>>>(nr);
    wcvt_kernel<<<(AREAS * KTP * SLAB_H + 255) / 256, 256>>>(W);

    for (int ch = 0; ch < NCHUNK; ch++) {
        const int row0 = ch * CHUNK_M;
        const int buf  = ch & 1;

        if (ch >= 2) cudaStreamWaitEvent(sP, evG[ch - 2], 0);
        permute_kernel<<<CHUNK_M / PR, 256, 0, sP>>>(x, row0, buf);
        cudaEventRecord(evP[ch], sP);

        cudaStreamWaitEvent(0, evP[ch], 0);
        gemm_kernel<<<dim3(MB_N, AREAS), 256, SMEM_BYTES>>>(bias, out, row0, buf);
        cudaEventRecord(evG[ch], 0);
    }
}